// round 7
// baseline (speedup 1.0000x reference)
#include <cuda_runtime.h>

typedef unsigned long long u64;

#define NNMAX 50000
#define INV_SQRT192 0.07216878364870323f
#define LN_EPS 1e-5f

// ---- packed f32x2 helpers (Blackwell sm_100a) ----
#define F2PACK(d, lo, hi) asm("mov.b64 %0, {%1, %2};" : "=l"(d) : "f"(lo), "f"(hi))
#define F2UNPACK(lo, hi, v) asm("mov.b64 {%0, %1}, %2;" : "=f"(lo), "=f"(hi) : "l"(v))
#define F2FMA(d, a, b, c) asm("fma.rn.f32x2 %0, %1, %2, %3;" : "=l"(d) : "l"(a), "l"(b), "l"(c))
#define F2ADD(d, a, b) asm("add.rn.f32x2 %0, %1, %2;" : "=l"(d) : "l"(a), "l"(b))
#define F2MUL(d, a, b) asm("mul.rn.f32x2 %0, %1, %2;" : "=l"(d) : "l"(a), "l"(b))

// ---------------- device scratch ----------------
__device__ float g_Q[NNMAX * 64];      // Q pre-scaled by 1/sqrt(192)
__device__ float g_K[NNMAX * 64];
__device__ float g_VU1[NNMAX * 192];   // V[n] @ Wu[0:64,:]
__device__ float g_VU2[NNMAX * 192];   // V[n] @ Wu[64:128,:]
__device__ float g_WEU[64 * 192];      // WE @ Wu[128:192,:]
__device__ float g_bEU[192];           // bu + bE @ Wu[128:192,:]

__global__ void zero_kernel(float* out, int n) {
    int i = blockIdx.x * blockDim.x + threadIdx.x;
    if (i < n) out[i] = 0.f;
}

__global__ void setup_kernel(const float* __restrict__ WE, const float* __restrict__ bE,
                             const float* __restrict__ Wu, const float* __restrict__ bu) {
    int id = blockIdx.x * blockDim.x + threadIdx.x;
    if (id < 64 * 192) {
        int k = id / 192, c = id % 192;
        float s = 0.f;
        #pragma unroll 8
        for (int r = 0; r < 64; r++) s += WE[k * 64 + r] * Wu[(128 + r) * 192 + c];
        g_WEU[id] = s;
    } else if (id < 64 * 192 + 192) {
        int c = id - 64 * 192;
        float s = bu[c];
        #pragma unroll 8
        for (int r = 0; r < 64; r++) s += bE[r] * Wu[(128 + r) * 192 + c];
        g_bEU[c] = s;
    }
}

// ---------------- node kernel (unchanged, proven) ----------------
#define NODE_SMEM ((128 * 192 + 64 * 384 + 12 * 256) * 4)

__global__ void __launch_bounds__(384, 1) node_kernel(
    const float* __restrict__ nf,
    const float* __restrict__ WQ, const float* __restrict__ bQ,
    const float* __restrict__ WK, const float* __restrict__ bK,
    const float* __restrict__ WV, const float* __restrict__ bV,
    const float* __restrict__ Wu, int N) {
    extern __shared__ float sm[];
    float* sW  = sm;
    float* sWu = sm + 128 * 192;
    float* sV  = sWu + 64 * 384;
    int tid = threadIdx.x;
    for (int i = tid; i < 128 * 192; i += 384) {
        int k = i / 192, c = i % 192;
        sW[i] = (c < 64) ? WQ[k * 64 + c] : (c < 128 ? WK[k * 64 + c - 64] : WV[k * 64 + c - 128]);
    }
    for (int i = tid; i < 64 * 384; i += 384) {
        int k = i / 384, c = i % 384;
        sWu[i] = (c < 192) ? Wu[k * 192 + c] : Wu[(64 + k) * 192 + (c - 192)];
    }
    __syncthreads();
    int wid = tid >> 5, j = tid & 31;
    float bq0 = bQ[j], bq1 = bQ[32 + j];
    float bk0 = bK[j], bk1 = bK[32 + j];
    float bv0 = bV[j], bv1 = bV[32 + j];
    float* myV = sV + wid * 256;
    int gw = blockIdx.x * 12 + wid;
    int stride = gridDim.x * 12 * 4;
    for (int base = gw * 4; base < N; base += stride) {
        float xr[4][4], acc[4][6];
        #pragma unroll
        for (int e = 0; e < 4; e++) {
            int n = base + e; if (n >= N) n = N - 1;
            #pragma unroll
            for (int s = 0; s < 4; s++) xr[e][s] = __ldg(nf + (long long)n * 128 + s * 32 + j);
            acc[e][0] = bq0; acc[e][1] = bq1; acc[e][2] = bk0;
            acc[e][3] = bk1; acc[e][4] = bv0; acc[e][5] = bv1;
        }
        #pragma unroll
        for (int s = 0; s < 4; s++) {
            #pragma unroll 4
            for (int k1 = 0; k1 < 32; k1++) {
                float x0 = __shfl_sync(0xffffffffu, xr[0][s], k1);
                float x1 = __shfl_sync(0xffffffffu, xr[1][s], k1);
                float x2 = __shfl_sync(0xffffffffu, xr[2][s], k1);
                float x3 = __shfl_sync(0xffffffffu, xr[3][s], k1);
                const float* wr = sW + (s * 32 + k1) * 192 + j;
                #pragma unroll
                for (int t = 0; t < 6; t++) {
                    float w = wr[32 * t];
                    acc[0][t] += x0 * w; acc[1][t] += x1 * w;
                    acc[2][t] += x2 * w; acc[3][t] += x3 * w;
                }
            }
        }
        __syncwarp();
        #pragma unroll
        for (int e = 0; e < 4; e++) {
            myV[e * 64 + j]      = acc[e][4];
            myV[e * 64 + 32 + j] = acc[e][5];
            int n = base + e;
            if (n < N) {
                g_Q[n * 64 + j]      = acc[e][0] * INV_SQRT192;
                g_Q[n * 64 + 32 + j] = acc[e][1] * INV_SQRT192;
                g_K[n * 64 + j]      = acc[e][2];
                g_K[n * 64 + 32 + j] = acc[e][3];
            }
        }
        __syncwarp();
        float vu[4][12];
        #pragma unroll
        for (int e = 0; e < 4; e++)
            #pragma unroll
            for (int t = 0; t < 12; t++) vu[e][t] = 0.f;
        #pragma unroll 4
        for (int k = 0; k < 64; k++) {
            float v0 = myV[0 * 64 + k];
            float v1 = myV[1 * 64 + k];
            float v2 = myV[2 * 64 + k];
            float v3 = myV[3 * 64 + k];
            const float* wr = sWu + k * 384 + j;
            #pragma unroll
            for (int t = 0; t < 12; t++) {
                float w = wr[32 * t];
                vu[0][t] += v0 * w; vu[1][t] += v1 * w;
                vu[2][t] += v2 * w; vu[3][t] += v3 * w;
            }
        }
        #pragma unroll
        for (int e = 0; e < 4; e++) {
            int n = base + e;
            if (n < N) {
                #pragma unroll
                for (int t = 0; t < 6; t++) {
                    g_VU1[n * 192 + 32 * t + j] = vu[e][t];
                    g_VU2[n * 192 + 32 * t + j] = vu[e][6 + t];
                }
            }
        }
    }
}

// ---------------- edge kernel v3: f32x2, 4 edges/warp, 12 warps/SM ----------------
#define OFF_WE    0        // [64][64]
#define OFF_WEU   4096     // [64][192]
#define OFF_WM    16384    // [192][128] packed [k][4*j + i] = Wm[k][32*i + j]
#define OFF_STAGE 40960    // 12 warps * 2 pairs * 192 u64 = 9216 floats (region 12288)
#define OFF_BE    53248
#define OFF_BEU   53312
#define OFF_G1    53504
#define OFF_B1    53696
#define OFF_BM    53888
#define OFF_G2    54016
#define OFF_B2    54144
#define EDGE_SMEM (54272 * 4)

#define EW 12   // edge-kernel warps per block

__global__ void __launch_bounds__(32 * EW, 1) edge_kernel(
    const float* __restrict__ edge_fea,
    const int* __restrict__ idx1, const int* __restrict__ idx2,
    const float* __restrict__ WE, const float* __restrict__ Wm,
    const float* __restrict__ bE, const float* __restrict__ bm,
    const float* __restrict__ g1, const float* __restrict__ b1,
    const float* __restrict__ g2, const float* __restrict__ b2,
    float* __restrict__ out, int Eq) {
    extern __shared__ float sm[];
    float* sWE  = sm + OFF_WE;
    float* sWEU = sm + OFF_WEU;
    float* sWm  = sm + OFF_WM;
    float* sbE  = sm + OFF_BE;
    float* sbEU = sm + OFF_BEU;
    float* sg1  = sm + OFF_G1;
    float* sb1  = sm + OFF_B1;
    float* sbm  = sm + OFF_BM;
    float* sg2  = sm + OFF_G2;
    float* sb2  = sm + OFF_B2;
    int tid = threadIdx.x;
    for (int i = tid; i < 4096;  i += 32 * EW) sWE[i]  = WE[i];
    for (int i = tid; i < 12288; i += 32 * EW) sWEU[i] = g_WEU[i];
    for (int i = tid; i < 24576; i += 32 * EW) {
        int k = i / 128, c = i % 128;
        sWm[k * 128 + 4 * (c & 31) + (c >> 5)] = Wm[i];
    }
    if (tid < 64)  sbE[tid] = bE[tid];
    if (tid < 192) { sbEU[tid] = g_bEU[tid]; sg1[tid] = g1[tid]; sb1[tid] = b1[tid]; }
    if (tid < 128) { sbm[tid] = bm[tid]; sg2[tid] = g2[tid]; sb2[tid] = b2[tid]; }
    __syncthreads();
    int wid = tid >> 5, j = tid & 31;
    u64* stageW = (u64*)(sm + OFF_STAGE) + wid * 384;   // [2 pairs][192]

    // hoisted packed (both halves identical) biases
    u64 bE2[2], bEU2[6], bm2[4];
    { float b0 = sbE[j], b1v = sbE[32 + j]; F2PACK(bE2[0], b0, b0); F2PACK(bE2[1], b1v, b1v); }
    #pragma unroll
    for (int t = 0; t < 6; t++) { float b = sbEU[32 * t + j]; F2PACK(bEU2[t], b, b); }
    #pragma unroll
    for (int i = 0; i < 4; i++) { float b = sbm[32 * i + j]; F2PACK(bm2[i], b, b); }

    int gw = blockIdx.x * EW + wid;
    int stride = gridDim.x * EW * 4;
    for (int base = gw * 4; base < Eq; base += stride) {
        int i1v[4], i2v[4];
        bool val[4];
        float ef[2][4];
        #pragma unroll
        for (int e = 0; e < 4; e++) {
            int ed = base + e;
            val[e] = (ed < Eq);
            if (!val[e]) ed = Eq - 1;
            i1v[e] = __ldg(idx1 + ed);
            i2v[e] = __ldg(idx2 + ed);
            ef[0][e] = __ldg(edge_fea + (long long)ed * 64 + j);
            ef[1][e] = __ldg(edge_fea + (long long)ed * 64 + 32 + j);
        }
        // ---- EC: ep = ef@WE + bE ; u = ef@WEU + bEU (packed edge-pairs) ----
        u64 ep2[2][2], u2[2][6];
        #pragma unroll
        for (int p = 0; p < 2; p++) {
            ep2[p][0] = bE2[0]; ep2[p][1] = bE2[1];
            #pragma unroll
            for (int t = 0; t < 6; t++) u2[p][t] = bEU2[t];
        }
        #pragma unroll
        for (int s = 0; s < 2; s++) {
            #pragma unroll 4
            for (int k1 = 0; k1 < 32; k1++) {
                int k = s * 32 + k1;
                float x[4];
                #pragma unroll
                for (int e = 0; e < 4; e++) x[e] = __shfl_sync(0xffffffffu, ef[s][e], k1);
                u64 xp[2];
                #pragma unroll
                for (int p = 0; p < 2; p++) F2PACK(xp[p], x[2 * p], x[2 * p + 1]);
                float we0 = sWE[k * 64 + j], we1 = sWE[k * 64 + 32 + j];
                u64 w0, w1; F2PACK(w0, we0, we0); F2PACK(w1, we1, we1);
                #pragma unroll
                for (int p = 0; p < 2; p++) {
                    F2FMA(ep2[p][0], xp[p], w0, ep2[p][0]);
                    F2FMA(ep2[p][1], xp[p], w1, ep2[p][1]);
                }
                const float* wu = sWEU + k * 192 + j;
                #pragma unroll
                for (int t = 0; t < 6; t++) {
                    float w = wu[32 * t];
                    u64 w2; F2PACK(w2, w, w);
                    #pragma unroll
                    for (int p = 0; p < 2; p++) F2FMA(u2[p][t], xp[p], w2, u2[p][t]);
                }
            }
        }
        // ---- gathers + aij ----
        u64 a2[2][6];
        #pragma unroll
        for (int p = 0; p < 2; p++) {
            long long o1l = (long long)i1v[2 * p] * 64 + j,     o2l = (long long)i2v[2 * p] * 64 + j;
            long long o1h = (long long)i1v[2 * p + 1] * 64 + j, o2h = (long long)i2v[2 * p + 1] * 64 + j;
            float q0l = __ldg(g_Q + o1l), q1l = __ldg(g_Q + o1l + 32);
            float q0h = __ldg(g_Q + o1h), q1h = __ldg(g_Q + o1h + 32);
            float k10l = __ldg(g_K + o1l), k11l = __ldg(g_K + o1l + 32);
            float k10h = __ldg(g_K + o1h), k11h = __ldg(g_K + o1h + 32);
            float k20l = __ldg(g_K + o2l), k21l = __ldg(g_K + o2l + 32);
            float k20h = __ldg(g_K + o2h), k21h = __ldg(g_K + o2h + 32);
            u64 q0_2, q1_2, ka0, ka1, kb0, kb1;
            F2PACK(q0_2, q0l, q0h); F2PACK(q1_2, q1l, q1h);
            F2PACK(ka0, k10l, k10h); F2PACK(ka1, k11l, k11h);
            F2PACK(kb0, k20l, k20h); F2PACK(kb1, k21l, k21h);
            F2MUL(a2[p][0], q0_2, ka0); F2MUL(a2[p][1], q1_2, ka1);
            F2MUL(a2[p][2], q0_2, kb0); F2MUL(a2[p][3], q1_2, kb1);
            F2MUL(a2[p][4], q0_2, ep2[p][0]); F2MUL(a2[p][5], q1_2, ep2[p][1]);
            long long v1l = (long long)i1v[2 * p] * 192 + j,     v2l = (long long)i2v[2 * p] * 192 + j;
            long long v1h = (long long)i1v[2 * p + 1] * 192 + j, v2h = (long long)i2v[2 * p + 1] * 192 + j;
            #pragma unroll
            for (int t = 0; t < 6; t++) {
                float vl = __ldg(g_VU1 + v1l + 32 * t) + __ldg(g_VU2 + v2l + 32 * t);
                float vh = __ldg(g_VU1 + v1h + 32 * t) + __ldg(g_VU2 + v2h + 32 * t);
                u64 v2p; F2PACK(v2p, vl, vh);
                F2ADD(u2[p][t], u2[p][t], v2p);
            }
        }
        // ---- LN1 + sigmoid gate -> mij (into a2) ----
        #pragma unroll
        for (int p = 0; p < 2; p++) {
            u64 s1_2 = 0ull, s2_2 = 0ull;
            #pragma unroll
            for (int t = 0; t < 6; t++) {
                F2ADD(s1_2, s1_2, a2[p][t]);
                F2FMA(s2_2, a2[p][t], a2[p][t], s2_2);
            }
            float s1lo, s1hi, s2lo, s2hi;
            F2UNPACK(s1lo, s1hi, s1_2); F2UNPACK(s2lo, s2hi, s2_2);
            #pragma unroll
            for (int o = 16; o > 0; o >>= 1) {
                s1lo += __shfl_xor_sync(0xffffffffu, s1lo, o);
                s1hi += __shfl_xor_sync(0xffffffffu, s1hi, o);
                s2lo += __shfl_xor_sync(0xffffffffu, s2lo, o);
                s2hi += __shfl_xor_sync(0xffffffffu, s2hi, o);
            }
            float mlo = s1lo * (1.f / 192.f), mhi = s1hi * (1.f / 192.f);
            float rlo = rsqrtf(s2lo * (1.f / 192.f) - mlo * mlo + LN_EPS);
            float rhi = rsqrtf(s2hi * (1.f / 192.f) - mhi * mhi + LN_EPS);
            u64 nm2, rs2;
            F2PACK(nm2, -mlo, -mhi); F2PACK(rs2, rlo, rhi);
            #pragma unroll
            for (int t = 0; t < 6; t++) {
                u64 xc, xn, an2;
                F2ADD(xc, a2[p][t], nm2);
                F2MUL(xn, xc, rs2);
                float g = sg1[32 * t + j], b = sb1[32 * t + j];
                u64 g2v, b2v; F2PACK(g2v, g, g); F2PACK(b2v, b, b);
                F2FMA(an2, xn, g2v, b2v);
                float anlo, anhi; F2UNPACK(anlo, anhi, an2);
                float glo = 1.f / (1.f + __expf(-anlo));
                float ghi = 1.f / (1.f + __expf(-anhi));
                u64 gate2; F2PACK(gate2, glo, ghi);
                F2MUL(a2[p][t], gate2, u2[p][t]);
            }
        }
        // ---- stage mij pairs to smem (per-warp private) ----
        #pragma unroll
        for (int p = 0; p < 2; p++)
            #pragma unroll
            for (int t = 0; t < 6; t++)
                stageW[p * 192 + 32 * t + j] = a2[p][t];
        __syncwarp();
        // ---- msg = mij@Wm + bm (broadcast mij from smem, packed FMA) ----
        u64 msg2[2][4];
        #pragma unroll
        for (int p = 0; p < 2; p++)
            #pragma unroll
            for (int i = 0; i < 4; i++) msg2[p][i] = bm2[i];
        #pragma unroll 2
        for (int k = 0; k < 192; k += 2) {
            float4 wA = *(const float4*)(sWm + k * 128 + 4 * j);
            float4 wB = *(const float4*)(sWm + (k + 1) * 128 + 4 * j);
            u64 wa[4], wb[4];
            F2PACK(wa[0], wA.x, wA.x); F2PACK(wa[1], wA.y, wA.y);
            F2PACK(wa[2], wA.z, wA.z); F2PACK(wa[3], wA.w, wA.w);
            F2PACK(wb[0], wB.x, wB.x); F2PACK(wb[1], wB.y, wB.y);
            F2PACK(wb[2], wB.z, wB.z); F2PACK(wb[3], wB.w, wB.w);
            #pragma unroll
            for (int p = 0; p < 2; p++) {
                ulonglong2 m = *(const ulonglong2*)(stageW + p * 192 + k);
                #pragma unroll
                for (int i = 0; i < 4; i++) F2FMA(msg2[p][i], m.x, wa[i], msg2[p][i]);
                #pragma unroll
                for (int i = 0; i < 4; i++) F2FMA(msg2[p][i], m.y, wb[i], msg2[p][i]);
            }
        }
        __syncwarp();
        // ---- LN2 + scatter-add ----
        #pragma unroll
        for (int p = 0; p < 2; p++) {
            u64 s1_2 = 0ull, s2_2 = 0ull;
            #pragma unroll
            for (int i = 0; i < 4; i++) {
                F2ADD(s1_2, s1_2, msg2[p][i]);
                F2FMA(s2_2, msg2[p][i], msg2[p][i], s2_2);
            }
            float s1lo, s1hi, s2lo, s2hi;
            F2UNPACK(s1lo, s1hi, s1_2); F2UNPACK(s2lo, s2hi, s2_2);
            #pragma unroll
            for (int o = 16; o > 0; o >>= 1) {
                s1lo += __shfl_xor_sync(0xffffffffu, s1lo, o);
                s1hi += __shfl_xor_sync(0xffffffffu, s1hi, o);
                s2lo += __shfl_xor_sync(0xffffffffu, s2lo, o);
                s2hi += __shfl_xor_sync(0xffffffffu, s2hi, o);
            }
            float mlo = s1lo * (1.f / 128.f), mhi = s1hi * (1.f / 128.f);
            float rlo = rsqrtf(s2lo * (1.f / 128.f) - mlo * mlo + LN_EPS);
            float rhi = rsqrtf(s2hi * (1.f / 128.f) - mhi * mhi + LN_EPS);
            u64 nm2, rs2;
            F2PACK(nm2, -mlo, -mhi); F2PACK(rs2, rlo, rhi);
            float* oplo = out + (long long)i1v[2 * p] * 128 + j;
            float* ophi = out + (long long)i1v[2 * p + 1] * 128 + j;
            bool vlo = val[2 * p], vhi = val[2 * p + 1];
            #pragma unroll
            for (int i = 0; i < 4; i++) {
                u64 xc, xn, v2o;
                F2ADD(xc, msg2[p][i], nm2);
                F2MUL(xn, xc, rs2);
                float g = sg2[32 * i + j], b = sb2[32 * i + j];
                u64 g2v, b2v; F2PACK(g2v, g, g); F2PACK(b2v, b, b);
                F2FMA(v2o, xn, g2v, b2v);
                float flo, fhi; F2UNPACK(flo, fhi, v2o);
                if (vlo) atomicAdd(oplo + 32 * i, flo);
                if (vhi) atomicAdd(ophi + 32 * i, fhi);
            }
        }
    }
}

extern "C" void kernel_launch(void* const* d_in, const int* in_sizes, int n_in,
                              void* d_out, int out_size) {
    const float* node_fea = (const float*)d_in[0];
    const int*   idx1     = (const int*)d_in[1];
    const int*   idx2     = (const int*)d_in[2];
    const float* edge_fea = (const float*)d_in[3];
    const float* WQ = (const float*)d_in[4];  const float* bQ = (const float*)d_in[5];
    const float* WK = (const float*)d_in[6];  const float* bK = (const float*)d_in[7];
    const float* WV = (const float*)d_in[8];  const float* bV = (const float*)d_in[9];
    const float* WE = (const float*)d_in[10]; const float* bE = (const float*)d_in[11];
    const float* Wu = (const float*)d_in[12]; const float* bu = (const float*)d_in[13];
    const float* Wm = (const float*)d_in[14]; const float* bm = (const float*)d_in[15];
    const float* g1 = (const float*)d_in[16]; const float* b1 = (const float*)d_in[17];
    const float* g2 = (const float*)d_in[18]; const float* b2 = (const float*)d_in[19];
    float* out = (float*)d_out;
    int N = in_sizes[0] / 128;
    int E = in_sizes[1];

    cudaFuncSetAttribute(node_kernel, cudaFuncAttributeMaxDynamicSharedMemorySize, NODE_SMEM);
    cudaFuncSetAttribute(edge_kernel, cudaFuncAttributeMaxDynamicSharedMemorySize, EDGE_SMEM);

    zero_kernel<<<(out_size + 511) / 512, 512>>>(out, out_size);
    setup_kernel<<<(64 * 192 + 192 + 255) / 256, 256>>>(WE, bE, Wu, bu);
    node_kernel<<<148, 384, NODE_SMEM>>>(node_fea, WQ, bQ, WK, bK, WV, bV, Wu, N);
    edge_kernel<<<148, 32 * EW, EDGE_SMEM>>>(edge_fea, idx1, idx2, WE, Wm, bE, bm,
                                             g1, b1, g2, b2, out, E);
}

// round 8
// speedup vs baseline: 1.2965x; 1.2965x over previous
#include <cuda_runtime.h>

#define NNMAX 50000
#define INV_SQRT192 0.07216878364870323f
#define LN_EPS 1e-5f

// ---------------- device scratch ----------------
__device__ float g_Q[NNMAX * 64];      // Q pre-scaled by 1/sqrt(192)
__device__ float g_K[NNMAX * 64];
__device__ float g_VU1[NNMAX * 192];   // V[n] @ Wu[0:64,:]
__device__ float g_VU2[NNMAX * 192];   // V[n] @ Wu[64:128,:]
__device__ float g_WEU[64 * 192];      // WE @ Wu[128:192,:]
__device__ float g_bEU[192];           // bu + bE @ Wu[128:192,:]

__global__ void zero_kernel(float* out, int n) {
    int i = blockIdx.x * blockDim.x + threadIdx.x;
    if (i < n) out[i] = 0.f;
}

__global__ void setup_kernel(const float* __restrict__ WE, const float* __restrict__ bE,
                             const float* __restrict__ Wu, const float* __restrict__ bu) {
    int id = blockIdx.x * blockDim.x + threadIdx.x;
    if (id < 64 * 192) {
        int k = id / 192, c = id % 192;
        float s = 0.f;
        #pragma unroll 8
        for (int r = 0; r < 64; r++) s += WE[k * 64 + r] * Wu[(128 + r) * 192 + c];
        g_WEU[id] = s;
    } else if (id < 64 * 192 + 192) {
        int c = id - 64 * 192;
        float s = bu[c];
        #pragma unroll 8
        for (int r = 0; r < 64; r++) s += bE[r] * Wu[(128 + r) * 192 + c];
        g_bEU[c] = s;
    }
}

// ---------------- node kernel (unchanged, proven) ----------------
#define NODE_SMEM ((128 * 192 + 64 * 384 + 12 * 256) * 4)

__global__ void __launch_bounds__(384, 1) node_kernel(
    const float* __restrict__ nf,
    const float* __restrict__ WQ, const float* __restrict__ bQ,
    const float* __restrict__ WK, const float* __restrict__ bK,
    const float* __restrict__ WV, const float* __restrict__ bV,
    const float* __restrict__ Wu, int N) {
    extern __shared__ float sm[];
    float* sW  = sm;
    float* sWu = sm + 128 * 192;
    float* sV  = sWu + 64 * 384;
    int tid = threadIdx.x;
    for (int i = tid; i < 128 * 192; i += 384) {
        int k = i / 192, c = i % 192;
        sW[i] = (c < 64) ? WQ[k * 64 + c] : (c < 128 ? WK[k * 64 + c - 64] : WV[k * 64 + c - 128]);
    }
    for (int i = tid; i < 64 * 384; i += 384) {
        int k = i / 384, c = i % 384;
        sWu[i] = (c < 192) ? Wu[k * 192 + c] : Wu[(64 + k) * 192 + (c - 192)];
    }
    __syncthreads();
    int wid = tid >> 5, j = tid & 31;
    float bq0 = bQ[j], bq1 = bQ[32 + j];
    float bk0 = bK[j], bk1 = bK[32 + j];
    float bv0 = bV[j], bv1 = bV[32 + j];
    float* myV = sV + wid * 256;
    int gw = blockIdx.x * 12 + wid;
    int stride = gridDim.x * 12 * 4;
    for (int base = gw * 4; base < N; base += stride) {
        float xr[4][4], acc[4][6];
        #pragma unroll
        for (int e = 0; e < 4; e++) {
            int n = base + e; if (n >= N) n = N - 1;
            #pragma unroll
            for (int s = 0; s < 4; s++) xr[e][s] = __ldg(nf + (long long)n * 128 + s * 32 + j);
            acc[e][0] = bq0; acc[e][1] = bq1; acc[e][2] = bk0;
            acc[e][3] = bk1; acc[e][4] = bv0; acc[e][5] = bv1;
        }
        #pragma unroll
        for (int s = 0; s < 4; s++) {
            #pragma unroll 4
            for (int k1 = 0; k1 < 32; k1++) {
                float x0 = __shfl_sync(0xffffffffu, xr[0][s], k1);
                float x1 = __shfl_sync(0xffffffffu, xr[1][s], k1);
                float x2 = __shfl_sync(0xffffffffu, xr[2][s], k1);
                float x3 = __shfl_sync(0xffffffffu, xr[3][s], k1);
                const float* wr = sW + (s * 32 + k1) * 192 + j;
                #pragma unroll
                for (int t = 0; t < 6; t++) {
                    float w = wr[32 * t];
                    acc[0][t] += x0 * w; acc[1][t] += x1 * w;
                    acc[2][t] += x2 * w; acc[3][t] += x3 * w;
                }
            }
        }
        __syncwarp();
        #pragma unroll
        for (int e = 0; e < 4; e++) {
            myV[e * 64 + j]      = acc[e][4];
            myV[e * 64 + 32 + j] = acc[e][5];
            int n = base + e;
            if (n < N) {
                g_Q[n * 64 + j]      = acc[e][0] * INV_SQRT192;
                g_Q[n * 64 + 32 + j] = acc[e][1] * INV_SQRT192;
                g_K[n * 64 + j]      = acc[e][2];
                g_K[n * 64 + 32 + j] = acc[e][3];
            }
        }
        __syncwarp();
        float vu[4][12];
        #pragma unroll
        for (int e = 0; e < 4; e++)
            #pragma unroll
            for (int t = 0; t < 12; t++) vu[e][t] = 0.f;
        #pragma unroll 4
        for (int k = 0; k < 64; k++) {
            float v0 = myV[0 * 64 + k];
            float v1 = myV[1 * 64 + k];
            float v2 = myV[2 * 64 + k];
            float v3 = myV[3 * 64 + k];
            const float* wr = sWu + k * 384 + j;
            #pragma unroll
            for (int t = 0; t < 12; t++) {
                float w = wr[32 * t];
                vu[0][t] += v0 * w; vu[1][t] += v1 * w;
                vu[2][t] += v2 * w; vu[3][t] += v3 * w;
            }
        }
        #pragma unroll
        for (int e = 0; e < 4; e++) {
            int n = base + e;
            if (n < N) {
                #pragma unroll
                for (int t = 0; t < 6; t++) {
                    g_VU1[n * 192 + 32 * t + j] = vu[e][t];
                    g_VU2[n * 192 + 32 * t + j] = vu[e][6 + t];
                }
            }
        }
    }
}

// ================= edge kernel v4: tf32 mma.sync tiles =================
// Per warp: one m16 tile = 16 edges. Block = 8 warps = 128 edges per tile-iter.
// GEMM1: ef[16,64] @ W1[64,256]  (cols 0:64 = WE -> ep, 64:256 = WEU -> u)
// GEMM2: mij[16,192] @ Wm[192,128]
// smem word offsets
#define SW1   0        // [256 n][68] tf32 (k-stride 68: bank = 4g+t, conflict-free)
#define SWM   17408    // [128 n][196] tf32
#define SBE   42496    // 64
#define SBEU  42560    // 192
#define SG1   42752    // 192
#define SB1   42944    // 192
#define SBM   43136    // 128
#define SG2   43264    // 128
#define SB2   43392    // 128
#define ESMEM_WORDS 43520
#define EDGE_SMEM (ESMEM_WORDS * 4)

__device__ __forceinline__ unsigned tf32_of(float f) {
    unsigned r; asm("cvt.rna.tf32.f32 %0, %1;" : "=r"(r) : "f"(f)); return r;
}

#define MMA_TF32(d, a0, a1, a2, a3, b0, b1) \
    asm volatile("mma.sync.aligned.m16n8k8.row.col.f32.tf32.tf32.f32 " \
        "{%0,%1,%2,%3}, {%4,%5,%6,%7}, {%8,%9}, {%0,%1,%2,%3};" \
        : "+f"(d[0]), "+f"(d[1]), "+f"(d[2]), "+f"(d[3]) \
        : "r"(a0), "r"(a1), "r"(a2), "r"(a3), "r"(b0), "r"(b1))

__global__ void __launch_bounds__(256, 1) edge_kernel(
    const float* __restrict__ edge_fea,
    const int* __restrict__ idx1, const int* __restrict__ idx2,
    const float* __restrict__ WE, const float* __restrict__ Wm,
    const float* __restrict__ bE, const float* __restrict__ bm,
    const float* __restrict__ g1, const float* __restrict__ b1,
    const float* __restrict__ g2, const float* __restrict__ b2,
    float* __restrict__ out, int E) {
    extern __shared__ float smf[];
    int tid = threadIdx.x;
    // ---- fill weights (tf32 bits stored in float slots) ----
    for (int i = tid; i < 256 * 64; i += 256) {
        int n = i >> 6, k = i & 63;
        float v = (n < 64) ? WE[k * 64 + n] : g_WEU[k * 192 + (n - 64)];
        ((unsigned*)smf)[SW1 + n * 68 + k] = tf32_of(v);
    }
    for (int i = tid; i < 128 * 192; i += 256) {
        int n = i / 192, k = i % 192;
        ((unsigned*)smf)[SWM + n * 196 + k] = tf32_of(Wm[k * 128 + n]);
    }
    if (tid < 64)  smf[SBE + tid] = bE[tid];
    if (tid < 192) { smf[SBEU + tid] = g_bEU[tid]; smf[SG1 + tid] = g1[tid]; smf[SB1 + tid] = b1[tid]; }
    if (tid < 128) { smf[SBM + tid] = bm[tid]; smf[SG2 + tid] = g2[tid]; smf[SB2 + tid] = b2[tid]; }
    __syncthreads();

    int wid = tid >> 5, lane = tid & 31;
    int g = lane >> 2, t = lane & 3;
    const unsigned* W1u = (const unsigned*)smf + SW1;
    const unsigned* Wmu = (const unsigned*)smf + SWM;
    int s_lo = (lane & ~3) | (t >> 1);
    int s_hi = s_lo + 2;
    bool odd = (t & 1) != 0;

    int nTiles = (E + 127) >> 7;
    for (int tile = blockIdx.x; tile < nTiles; tile += gridDim.x) {
        int e0 = tile * 128 + wid * 16 + g;   // row g
        int e1 = e0 + 8;                       // row g+8
        int eA = min(e0, E - 1), eB = min(e1, E - 1);
        bool vA = (e0 < E), vB = (e1 < E);
        int i1A = __ldg(idx1 + eA), i2A = __ldg(idx2 + eA);
        int i1B = __ldg(idx1 + eB), i2B = __ldg(idx2 + eB);

        // ---- GEMM1: ep[8 n-tiles], uu[24 n-tiles] ----
        float ep[8][4], uu[24][4];
        #pragma unroll
        for (int nt = 0; nt < 8; nt++) { ep[nt][0] = ep[nt][1] = ep[nt][2] = ep[nt][3] = 0.f; }
        #pragma unroll
        for (int nt = 0; nt < 24; nt++) { uu[nt][0] = uu[nt][1] = uu[nt][2] = uu[nt][3] = 0.f; }
        const float* efA = edge_fea + (long long)eA * 64;
        const float* efB = edge_fea + (long long)eB * 64;
        #pragma unroll 1
        for (int kt = 0; kt < 8; kt++) {
            int kb = kt * 8 + t;
            unsigned a0 = tf32_of(__ldg(efA + kb));
            unsigned a2 = tf32_of(__ldg(efA + kb + 4));
            unsigned a1 = tf32_of(__ldg(efB + kb));
            unsigned a3 = tf32_of(__ldg(efB + kb + 4));
            const unsigned* wp = W1u + g * 68 + kb;
            #pragma unroll
            for (int nt = 0; nt < 8; nt++) {
                unsigned b0 = wp[nt * 544], b1 = wp[nt * 544 + 4];   // 544 = 8*68
                MMA_TF32(ep[nt], a0, a1, a2, a3, b0, b1);
            }
            #pragma unroll
            for (int nt = 0; nt < 24; nt++) {
                unsigned b0 = wp[(8 + nt) * 544], b1 = wp[(8 + nt) * 544 + 4];
                MMA_TF32(uu[nt], a0, a1, a2, a3, b0, b1);
            }
        }

        // ---- per-edge glue: gathers, LN1 stats (64-dim dots), gate, VU add ----
        #pragma unroll
        for (int slot = 0; slot < 2; slot++) {
            int i1 = slot ? i1B : i1A;
            int i2 = slot ? i2B : i2A;
            const float2* Qp  = (const float2*)(g_Q + (long long)i1 * 64) + t;
            const float2* K1p = (const float2*)(g_K + (long long)i1 * 64) + t;
            const float2* K2p = (const float2*)(g_K + (long long)i2 * 64) + t;
            float2 q2[8], k12[8], k22[8];
            #pragma unroll
            for (int j = 0; j < 8; j++) {
                q2[j]  = __ldg(Qp + j * 4);
                k12[j] = __ldg(K1p + j * 4);
                k22[j] = __ldg(K2p + j * 4);
            }
            float s1 = 0.f, s2 = 0.f;
            #pragma unroll
            for (int j = 0; j < 8; j++) {
                float2 be = *(const float2*)(smf + SBE + 8 * j + 2 * t);
                float ex = ep[j][2 * slot] + be.x, ey = ep[j][2 * slot + 1] + be.y;
                float ksx = k12[j].x + k22[j].x + ex;
                float ksy = k12[j].y + k22[j].y + ey;
                s1 += q2[j].x * ksx + q2[j].y * ksy;
                float qx2 = q2[j].x * q2[j].x, qy2 = q2[j].y * q2[j].y;
                s2 += qx2 * (k12[j].x * k12[j].x + k22[j].x * k22[j].x + ex * ex)
                    + qy2 * (k12[j].y * k12[j].y + k22[j].y * k22[j].y + ey * ey);
            }
            s1 += __shfl_xor_sync(0xffffffffu, s1, 1);
            s1 += __shfl_xor_sync(0xffffffffu, s1, 2);
            s2 += __shfl_xor_sync(0xffffffffu, s2, 1);
            s2 += __shfl_xor_sync(0xffffffffu, s2, 2);
            float mean = s1 * (1.f / 192.f);
            float var  = s2 * (1.f / 192.f) - mean * mean;
            float rs = rsqrtf(var + LN_EPS);
            const float2* V1p = (const float2*)(g_VU1 + (long long)i1 * 192) + t;
            const float2* V2p = (const float2*)(g_VU2 + (long long)i2 * 192) + t;
            #pragma unroll
            for (int nt = 0; nt < 24; nt++) {
                int j = nt & 7, chunk = nt >> 3;
                float kx, ky;
                if (chunk == 0)      { kx = k12[j].x; ky = k12[j].y; }
                else if (chunk == 1) { kx = k22[j].x; ky = k22[j].y; }
                else {
                    float2 be = *(const float2*)(smf + SBE + 8 * j + 2 * t);
                    kx = ep[j][2 * slot] + be.x; ky = ep[j][2 * slot + 1] + be.y;
                }
                int cu = nt * 8 + 2 * t;
                float ax = q2[j].x * kx, ay = q2[j].y * ky;
                float2 g1v = *(const float2*)(smf + SG1 + cu);
                float2 b1v = *(const float2*)(smf + SB1 + cu);
                float nx = (ax - mean) * rs * g1v.x + b1v.x;
                float ny = (ay - mean) * rs * g1v.y + b1v.y;
                float gx = 1.f / (1.f + __expf(-nx));
                float gy = 1.f / (1.f + __expf(-ny));
                float2 beu = *(const float2*)(smf + SBEU + cu);
                float2 w1 = __ldg(V1p + nt * 4);
                float2 w2 = __ldg(V2p + nt * 4);
                uu[nt][2 * slot]     = gx * (uu[nt][2 * slot]     + beu.x + w1.x + w2.x);
                uu[nt][2 * slot + 1] = gy * (uu[nt][2 * slot + 1] + beu.y + w1.y + w2.y);
            }
        }

        // ---- GEMM2: msg = mij @ Wm (A from shfl of uu fragments) ----
        float msg[16][4];
        #pragma unroll
        for (int nt = 0; nt < 16; nt++) { msg[nt][0] = msg[nt][1] = msg[nt][2] = msg[nt][3] = 0.f; }
        #pragma unroll
        for (int kt = 0; kt < 24; kt++) {
            float v00 = __shfl_sync(0xffffffffu, uu[kt][0], s_lo);
            float v01 = __shfl_sync(0xffffffffu, uu[kt][1], s_lo);
            float v10 = __shfl_sync(0xffffffffu, uu[kt][2], s_lo);
            float v11 = __shfl_sync(0xffffffffu, uu[kt][3], s_lo);
            float v20 = __shfl_sync(0xffffffffu, uu[kt][0], s_hi);
            float v21 = __shfl_sync(0xffffffffu, uu[kt][1], s_hi);
            float v30 = __shfl_sync(0xffffffffu, uu[kt][2], s_hi);
            float v31 = __shfl_sync(0xffffffffu, uu[kt][3], s_hi);
            unsigned a0 = tf32_of(odd ? v01 : v00);
            unsigned a1 = tf32_of(odd ? v11 : v10);
            unsigned a2 = tf32_of(odd ? v21 : v20);
            unsigned a3 = tf32_of(odd ? v31 : v30);
            const unsigned* wp = Wmu + g * 196 + kt * 8 + t;
            #pragma unroll
            for (int nt = 0; nt < 16; nt++) {
                unsigned b0 = wp[nt * 1568], b1 = wp[nt * 1568 + 4];   // 1568 = 8*196
                MMA_TF32(msg[nt], a0, a1, a2, a3, b0, b1);
            }
        }

        // ---- +bm, LN2, scatter (red.v2) ----
        #pragma unroll
        for (int nt = 0; nt < 16; nt++) {
            float2 bmv = *(const float2*)(smf + SBM + nt * 8 + 2 * t);
            msg[nt][0] += bmv.x; msg[nt][1] += bmv.y;
            msg[nt][2] += bmv.x; msg[nt][3] += bmv.y;
        }
        #pragma unroll
        for (int slot = 0; slot < 2; slot++) {
            float s1 = 0.f, s2 = 0.f;
            #pragma unroll
            for (int nt = 0; nt < 16; nt++) {
                float x = msg[nt][2 * slot], y = msg[nt][2 * slot + 1];
                s1 += x + y; s2 += x * x + y * y;
            }
            s1 += __shfl_xor_sync(0xffffffffu, s1, 1);
            s1 += __shfl_xor_sync(0xffffffffu, s1, 2);
            s2 += __shfl_xor_sync(0xffffffffu, s2, 1);
            s2 += __shfl_xor_sync(0xffffffffu, s2, 2);
            float mean = s1 * (1.f / 128.f);
            float var  = s2 * (1.f / 128.f) - mean * mean;
            float rs = rsqrtf(var + LN_EPS);
            int i1 = slot ? i1B : i1A;
            bool v = slot ? vB : vA;
            float* op = out + (long long)i1 * 128 + 2 * t;
            #pragma unroll
            for (int nt = 0; nt < 16; nt++) {
                float2 g2v = *(const float2*)(smf + SG2 + nt * 8 + 2 * t);
                float2 b2v = *(const float2*)(smf + SB2 + nt * 8 + 2 * t);
                float ox = (msg[nt][2 * slot]     - mean) * rs * g2v.x + b2v.x;
                float oy = (msg[nt][2 * slot + 1] - mean) * rs * g2v.y + b2v.y;
                if (v) {
                    asm volatile("red.global.add.v2.f32 [%0], {%1,%2};"
                                 :: "l"(op + nt * 8), "f"(ox), "f"(oy) : "memory");
                }
            }
        }
    }
}

extern "C" void kernel_launch(void* const* d_in, const int* in_sizes, int n_in,
                              void* d_out, int out_size) {
    const float* node_fea = (const float*)d_in[0];
    const int*   idx1     = (const int*)d_in[1];
    const int*   idx2     = (const int*)d_in[2];
    const float* edge_fea = (const float*)d_in[3];
    const float* WQ = (const float*)d_in[4];  const float* bQ = (const float*)d_in[5];
    const float* WK = (const float*)d_in[6];  const float* bK = (const float*)d_in[7];
    const float* WV = (const float*)d_in[8];  const float* bV = (const float*)d_in[9];
    const float* WE = (const float*)d_in[10]; const float* bE = (const float*)d_in[11];
    const float* Wu = (const float*)d_in[12]; const float* bu = (const float*)d_in[13];
    const float* Wm = (const float*)d_in[14]; const float* bm = (const float*)d_in[15];
    const float* g1 = (const float*)d_in[16]; const float* b1 = (const float*)d_in[17];
    const float* g2 = (const float*)d_in[18]; const float* b2 = (const float*)d_in[19];
    float* out = (float*)d_out;
    int N = in_sizes[0] / 128;
    int E = in_sizes[1];

    cudaFuncSetAttribute(node_kernel, cudaFuncAttributeMaxDynamicSharedMemorySize, NODE_SMEM);
    cudaFuncSetAttribute(edge_kernel, cudaFuncAttributeMaxDynamicSharedMemorySize, EDGE_SMEM);

    zero_kernel<<<(out_size + 511) / 512, 512>>>(out, out_size);
    setup_kernel<<<(64 * 192 + 192 + 255) / 256, 256>>>(WE, bE, Wu, bu);
    node_kernel<<<148, 384, NODE_SMEM>>>(node_fea, WQ, bQ, WK, bK, WV, bV, Wu, N);
    edge_kernel<<<148, 256, EDGE_SMEM>>>(edge_fea, idx1, idx2, WE, Wm, bE, bm,
                                         g1, b1, g2, b2, out, E);
}